// round 1
// baseline (speedup 1.0000x reference)
#include <cuda_runtime.h>

#define B_DIM 512
#define IN_DIM 512
#define OUT_DIM 1024
#define TM 64
#define TN 64
#define TK 32

// Tropical (min-plus) matmul: out[m, n] = min_k (x[m,k] + w[n,k])
// x: [512, 512] row-major, w: [1024, 512] row-major, out: [512, 1024]
//
// 64x64 output tile per CTA, 256 threads, 4x4 register tile per thread.
// Shared tiles stored k-major with XOR swizzle (col ^ (k & 28)) so that both
// the transposed scalar STS from float4 global loads AND the float4 LDS in the
// inner loop are bank-conflict-free.
__global__ __launch_bounds__(256, 1)
void tropical_mm_kernel(const float* __restrict__ x,
                        const float* __restrict__ w,
                        float* __restrict__ out)
{
    __shared__ float xs[TK][TM];  // xs[k][m ^ (k&28)] = x[m0+m][k0+k]
    __shared__ float ws[TK][TN];  // ws[k][n ^ (k&28)] = w[n0+n][k0+k]

    const int tid = threadIdx.x;
    const int tx = tid & 15;      // n-group (4 outputs)
    const int ty = tid >> 4;      // m-group (4 outputs)
    const int m0 = blockIdx.y * TM;
    const int n0 = blockIdx.x * TN;

    const float INF = __int_as_float(0x7f800000);
    float acc[4][4];
#pragma unroll
    for (int i = 0; i < 4; i++)
#pragma unroll
        for (int j = 0; j < 4; j++) acc[i][j] = INF;

    for (int k0 = 0; k0 < IN_DIM; k0 += TK) {
        // Cooperative load: 64 rows x 32 k per tile for both x and w.
        // 512 float4 loads per tensor per tile -> 2 rounds of 256 threads.
#pragma unroll
        for (int r = 0; r < 2; r++) {
            int t   = tid + r * 256;
            int row = t >> 3;          // 0..63
            int kc  = (t & 7) << 2;    // 0,4,...,28 ; swizzle c = kc for these 4 k's
            int col = row ^ kc;        // conflict-free STS column

            float4 xv = *reinterpret_cast<const float4*>(&x[(m0 + row) * IN_DIM + k0 + kc]);
            xs[kc + 0][col] = xv.x;
            xs[kc + 1][col] = xv.y;
            xs[kc + 2][col] = xv.z;
            xs[kc + 3][col] = xv.w;

            float4 wv = *reinterpret_cast<const float4*>(&w[(n0 + row) * IN_DIM + k0 + kc]);
            ws[kc + 0][col] = wv.x;
            ws[kc + 1][col] = wv.y;
            ws[kc + 2][col] = wv.z;
            ws[kc + 3][col] = wv.w;
        }
        __syncthreads();

#pragma unroll
        for (int k = 0; k < TK; k++) {
            const int c = k & 28;
            float4 xv = *reinterpret_cast<const float4*>(&xs[k][(ty << 2) ^ c]);
            float4 wv = *reinterpret_cast<const float4*>(&ws[k][(tx << 2) ^ c]);
            float xm[4] = {xv.x, xv.y, xv.z, xv.w};
            float wn[4] = {wv.x, wv.y, wv.z, wv.w};
#pragma unroll
            for (int i = 0; i < 4; i++)
#pragma unroll
                for (int j = 0; j < 4; j++)
                    acc[i][j] = fminf(acc[i][j], xm[i] + wn[j]);
        }
        __syncthreads();
    }

    // Epilogue: each thread writes 4 rows of float4
#pragma unroll
    for (int i = 0; i < 4; i++) {
        float4 o = make_float4(acc[i][0], acc[i][1], acc[i][2], acc[i][3]);
        *reinterpret_cast<float4*>(&out[(m0 + (ty << 2) + i) * OUT_DIM + n0 + (tx << 2)]) = o;
    }
}

extern "C" void kernel_launch(void* const* d_in, const int* in_sizes, int n_in,
                              void* d_out, int out_size)
{
    const float* x = (const float*)d_in[0];   // [512, 512]
    const float* w = (const float*)d_in[1];   // [1024, 512]
    float* out = (float*)d_out;               // [512, 1024]

    dim3 grid(OUT_DIM / TN, B_DIM / TM);      // (16, 8) = 128 CTAs
    dim3 block(256);
    tropical_mm_kernel<<<grid, block>>>(x, w, out);
}

// round 2
// speedup vs baseline: 1.1606x; 1.1606x over previous
#include <cuda_runtime.h>

#define B_DIM 512
#define IN_DIM 512
#define OUT_DIM 1024
#define TM 64
#define TN 32
#define TK 32

// Tropical (min-plus) matmul: out[m, n] = min_k (x[m,k] + w[n,k])
// x: [512, 512], w: [1024, 512], out: [512, 1024], all row-major fp32.
//
// CTA tile 64(m) x 32(n), 256 threads, 4x2 register tile per thread.
// Grid = 32 x 8 = 256 CTAs -> 2048 warps total (~14 warps/SM resident).
// Shared tiles stored k-major with XOR swizzle col = row ^ (k & 28):
// conflict-free for both the transposed STS and the vectorized LDS.
// Global loads for the next k-tile are register-double-buffered so LDG
// latency overlaps the 32-k compute loop.
__global__ __launch_bounds__(256, 2)
void tropical_mm_kernel(const float* __restrict__ x,
                        const float* __restrict__ w,
                        float* __restrict__ out)
{
    __shared__ float xs[TK][TM];  // xs[k][m ^ (k&28)]
    __shared__ float ws[TK][TN];  // ws[k][n ^ (k&28)]

    const int tid = threadIdx.x;
    const int tx = tid & 15;      // n-group: 2 outputs  -> covers 32
    const int ty = tid >> 4;      // m-group: 4 outputs  -> covers 64
    const int m0 = blockIdx.y * TM;
    const int n0 = blockIdx.x * TN;

    // Cooperative-load coordinates (float4 granularity)
    const int lr = tid >> 3;         // 0..31
    const int lk = (tid & 7) << 2;   // 0,4,...,28
    const int xc0 = lr ^ lk;         // swizzled column for x row lr
    // row lr+32: (lr+32)^lk == (lr^lk)+32 since lk < 32
    const int wc0 = lr ^ lk;         // swizzled column for w row lr (0..31)

    const float* xg0 = &x[(m0 + lr) * IN_DIM + lk];
    const float* xg1 = &x[(m0 + lr + 32) * IN_DIM + lk];
    const float* wg  = &w[(n0 + lr) * IN_DIM + lk];

    // Precomputed swizzled LDS columns: class c = k & 28, index i = k >> 2
    int xcol[8], wcol[8];
#pragma unroll
    for (int i = 0; i < 8; i++) {
        xcol[i] = (ty << 2) ^ (i << 2);
        wcol[i] = (tx << 1) ^ (i << 2);
    }

    const float INF = __int_as_float(0x7f800000);
    float acc[4][2];
#pragma unroll
    for (int i = 0; i < 4; i++) {
        acc[i][0] = INF;
        acc[i][1] = INF;
    }

    // Prologue: load first tile into registers
    float4 xa = *reinterpret_cast<const float4*>(xg0);
    float4 xb = *reinterpret_cast<const float4*>(xg1);
    float4 wa = *reinterpret_cast<const float4*>(wg);

    for (int k0 = 0; k0 < IN_DIM; k0 += TK) {
        // Store current tile to shared (swizzled, k-major)
        xs[lk + 0][xc0] = xa.x;
        xs[lk + 1][xc0] = xa.y;
        xs[lk + 2][xc0] = xa.z;
        xs[lk + 3][xc0] = xa.w;
        xs[lk + 0][xc0 + 32] = xb.x;
        xs[lk + 1][xc0 + 32] = xb.y;
        xs[lk + 2][xc0 + 32] = xb.z;
        xs[lk + 3][xc0 + 32] = xb.w;
        ws[lk + 0][wc0] = wa.x;
        ws[lk + 1][wc0] = wa.y;
        ws[lk + 2][wc0] = wa.z;
        ws[lk + 3][wc0] = wa.w;
        __syncthreads();

        // Kick off next tile's global loads (hidden behind compute)
        if (k0 + TK < IN_DIM) {
            xg0 += TK; xg1 += TK; wg += TK;
            xa = *reinterpret_cast<const float4*>(xg0);
            xb = *reinterpret_cast<const float4*>(xg1);
            wa = *reinterpret_cast<const float4*>(wg);
        }

#pragma unroll
        for (int k = 0; k < TK; k++) {
            float4 xv = *reinterpret_cast<const float4*>(&xs[k][xcol[k >> 2]]);
            float2 wv = *reinterpret_cast<const float2*>(&ws[k][wcol[k >> 2]]);
            acc[0][0] = fminf(acc[0][0], xv.x + wv.x);
            acc[0][1] = fminf(acc[0][1], xv.x + wv.y);
            acc[1][0] = fminf(acc[1][0], xv.y + wv.x);
            acc[1][1] = fminf(acc[1][1], xv.y + wv.y);
            acc[2][0] = fminf(acc[2][0], xv.z + wv.x);
            acc[2][1] = fminf(acc[2][1], xv.z + wv.y);
            acc[3][0] = fminf(acc[3][0], xv.w + wv.x);
            acc[3][1] = fminf(acc[3][1], xv.w + wv.y);
        }
        __syncthreads();
    }

    // Epilogue: 4 rows of float2 per thread
#pragma unroll
    for (int i = 0; i < 4; i++) {
        float2 o = make_float2(acc[i][0], acc[i][1]);
        *reinterpret_cast<float2*>(&out[(m0 + (ty << 2) + i) * OUT_DIM + n0 + (tx << 1)]) = o;
    }
}

extern "C" void kernel_launch(void* const* d_in, const int* in_sizes, int n_in,
                              void* d_out, int out_size)
{
    const float* x = (const float*)d_in[0];   // [512, 512]
    const float* w = (const float*)d_in[1];   // [1024, 512]
    float* out = (float*)d_out;               // [512, 1024]

    dim3 grid(OUT_DIM / TN, B_DIM / TM);      // (32, 8) = 256 CTAs
    dim3 block(256);
    tropical_mm_kernel<<<grid, block>>>(x, w, out);
}